// round 1
// baseline (speedup 1.0000x reference)
#include <cuda_runtime.h>
#include <math.h>

// ---------------- problem constants ----------------
// inputs (metadata order):
// 0 inputs (1,128) f32        1 memory (4096,256) f32
// 2 conv_kernel1 (3,3,256,32) 3 conv_kernel2 (3,3,32,64)
// 4 conv_dense1 (238144,128)  5 conv_dense2 (128,256)
// 6 context_kernel (384,256)  7 recurr_kernel (384,256)
// 8 x (int)                   9 y (int)
// out: [c_t(256), r_t(256), new_mem(256*4096)] = 1049088 f32

#define C0 256
#define C1 32
#define FLATN 238144

// ---------------- device scratch ----------------
__device__ float g_c1[64 * 64 * 32];   // [pixel=h*64+w][co]
__device__ float g_c2[64 * 62 * 62];   // [co2][i][j]
__device__ float g_flat[FLATN];
__device__ float g_r1[128];
__device__ float g_rt[256];
__device__ float g_qt[256];
__device__ float g_st[256];
__device__ float g_scores[4096];
__device__ float g_at[4096];
__device__ float g_ct[256];
__device__ float g_memt[256];

// ---------------- zero scratch (must run every replay) ----------------
__global__ void zero_kernel() {
    int i = blockIdx.x * blockDim.x + threadIdx.x;
    if (i < 64 * 64 * 32) g_c1[i] = 0.f;
    if (i < 128) g_r1[i] = 0.f;
    if (i < 256) g_ct[i] = 0.f;
}

// ---------------- conv1: 3x3 SAME, 256->32 ----------------
// grid (64 rows, 8 ci-chunks of 32), block 256.
// warp lane = co (0..31); warp wq owns pixels w = wq*8 .. wq*8+7.
// smem input layout [ci][row][wp] (wp = w+1, padded 0..67), weights [ci][kk][co].
__global__ void conv1_kernel(const float* __restrict__ mem, const float* __restrict__ k1) {
    __shared__ __align__(16) float s_in[16 * 3 * 68];
    __shared__ float s_wt[16 * 9 * 32];
    int h = blockIdx.x;
    int chunk = blockIdx.y;
    int t = threadIdx.x;
    int lane = t & 31;
    int wq = t >> 5;
    float acc[8];
#pragma unroll
    for (int p = 0; p < 8; p++) acc[p] = 0.f;

    for (int sub = 0; sub < 2; sub++) {
        int ci0 = chunk * 32 + sub * 16;
        // weights: k1[kh][kw][ci][co] -> s_wt[ci*288 + kk*32 + co]
        for (int i = t; i < 16 * 9 * 32; i += 256) {
            int co = i & 31;
            int kk = (i >> 5) % 9;
            int ci = i / 288;
            s_wt[i] = k1[((size_t)kk * C0 + ci0 + ci) * C1 + co];
        }
        // inputs: memory[(hh*64+ww)*256 + ci]  (ci fastest -> coalesced)
        for (int i = t; i < 16 * 3 * 68; i += 256) {
            int ci = i & 15;
            int rest = i >> 4;
            int wp = rest % 68;
            int r = rest / 68;
            int hh = h + r - 1;
            int ww = wp - 1;
            float v = 0.f;
            if (hh >= 0 && hh < 64 && ww >= 0 && ww < 64)
                v = mem[((size_t)hh * 64 + ww) * C0 + ci0 + ci];
            s_in[ci * 204 + r * 68 + wp] = v;
        }
        __syncthreads();
#pragma unroll 1
        for (int ci = 0; ci < 16; ci++) {
            float wgt[9];
#pragma unroll
            for (int kk = 0; kk < 9; kk++) wgt[kk] = s_wt[ci * 288 + kk * 32 + lane];
            float inv[3][12];
#pragma unroll
            for (int r = 0; r < 3; r++) {
                const float4* p4 = (const float4*)&s_in[ci * 204 + r * 68 + wq * 8];
                float4 a = p4[0], b = p4[1], c = p4[2];
                inv[r][0] = a.x; inv[r][1] = a.y; inv[r][2] = a.z; inv[r][3] = a.w;
                inv[r][4] = b.x; inv[r][5] = b.y; inv[r][6] = b.z; inv[r][7] = b.w;
                inv[r][8] = c.x; inv[r][9] = c.y; inv[r][10] = c.z; inv[r][11] = c.w;
            }
#pragma unroll
            for (int kh = 0; kh < 3; kh++)
#pragma unroll
                for (int kw = 0; kw < 3; kw++) {
                    float wv = wgt[kh * 3 + kw];
#pragma unroll
                    for (int p = 0; p < 8; p++)
                        acc[p] = fmaf(inv[kh][p + kw], wv, acc[p]);
                }
        }
        __syncthreads();
    }
    int wbase = wq * 8;
#pragma unroll
    for (int p = 0; p < 8; p++)
        atomicAdd(&g_c1[((size_t)h * 64 + wbase + p) * 32 + lane], acc[p]);
}

// ---------------- conv2: 3x3 VALID, 32->64 ----------------
// grid (62 rows, 2 co-halves), block 256. lane = co within half.
__global__ void conv2_kernel(const float* __restrict__ k2) {
    __shared__ __align__(16) float s_in[16 * 3 * 68];
    __shared__ float s_wt[16 * 9 * 32];
    int i0 = blockIdx.x;    // output row 0..61
    int half = blockIdx.y;  // co2 half
    int t = threadIdx.x;
    int lane = t & 31;
    int wq = t >> 5;
    float acc[8];
#pragma unroll
    for (int p = 0; p < 8; p++) acc[p] = 0.f;

    for (int sub = 0; sub < 2; sub++) {
        int ci0 = sub * 16;
        for (int i = t; i < 16 * 9 * 32; i += 256) {
            int co = i & 31;
            int kk = (i >> 5) % 9;
            int ci = i / 288;
            s_wt[i] = k2[((size_t)kk * 32 + ci0 + ci) * 64 + half * 32 + co];
        }
        for (int i = t; i < 16 * 3 * 68; i += 256) {
            int ci = i & 15;
            int rest = i >> 4;
            int wp = rest % 68;
            int r = rest / 68;
            float v = 0.f;
            if (wp < 64) v = g_c1[(((size_t)(i0 + r)) * 64 + wp) * 32 + ci0 + ci];
            s_in[ci * 204 + r * 68 + wp] = v;
        }
        __syncthreads();
#pragma unroll 1
        for (int ci = 0; ci < 16; ci++) {
            float wgt[9];
#pragma unroll
            for (int kk = 0; kk < 9; kk++) wgt[kk] = s_wt[ci * 288 + kk * 32 + lane];
            float inv[3][12];
#pragma unroll
            for (int r = 0; r < 3; r++) {
                const float4* p4 = (const float4*)&s_in[ci * 204 + r * 68 + wq * 8];
                float4 a = p4[0], b = p4[1], c = p4[2];
                inv[r][0] = a.x; inv[r][1] = a.y; inv[r][2] = a.z; inv[r][3] = a.w;
                inv[r][4] = b.x; inv[r][5] = b.y; inv[r][6] = b.z; inv[r][7] = b.w;
                inv[r][8] = c.x; inv[r][9] = c.y; inv[r][10] = c.z; inv[r][11] = c.w;
            }
#pragma unroll
            for (int kh = 0; kh < 3; kh++)
#pragma unroll
                for (int kw = 0; kw < 3; kw++) {
                    float wv = wgt[kh * 3 + kw];
#pragma unroll
                    for (int p = 0; p < 8; p++)
                        acc[p] = fmaf(inv[kh][p + kw], wv, acc[p]);
                }
        }
        __syncthreads();
    }
    int co2 = half * 32 + lane;
#pragma unroll
    for (int p = 0; p < 8; p++) {
        int j = wq * 8 + p;
        if (j < 62) g_c2[(size_t)co2 * 3844 + i0 * 62 + j] = acc[p];
    }
}

// ---------------- 2x2 sum-pool * 0.25 -> flat ----------------
__global__ void pool_kernel() {
    int idx = blockIdx.x * 256 + threadIdx.x;
    if (idx >= FLATN) return;
    int c = idx / 3721;
    int rem = idx - c * 3721;
    int ph = rem / 61;
    int pw = rem - ph * 61;
    const float* b = &g_c2[(size_t)c * 3844 + ph * 62 + pw];
    g_flat[idx] = 0.25f * (b[0] + b[1] + b[62] + b[63]);
}

// ---------------- dense1: r1[128] = flat @ D1 (122 MB stream) ----------------
__global__ void dense1_kernel(const float* __restrict__ D1) {
    int t = threadIdx.x;
    int wq = t >> 5, lane = t & 31;
    float4 acc = make_float4(0.f, 0.f, 0.f, 0.f);
    const float4* D4 = (const float4*)D1;
#pragma unroll 4
    for (int row = blockIdx.x * 8 + wq; row < FLATN; row += 296 * 8) {
        float v = g_flat[row];
        float4 d = D4[(size_t)row * 32 + lane];
        acc.x = fmaf(v, d.x, acc.x);
        acc.y = fmaf(v, d.y, acc.y);
        acc.z = fmaf(v, d.z, acc.z);
        acc.w = fmaf(v, d.w, acc.w);
    }
    __shared__ float s[128];
    if (t < 128) s[t] = 0.f;
    __syncthreads();
    atomicAdd(&s[lane * 4 + 0], acc.x);
    atomicAdd(&s[lane * 4 + 1], acc.y);
    atomicAdd(&s[lane * 4 + 2], acc.z);
    atomicAdd(&s[lane * 4 + 3], acc.w);
    __syncthreads();
    if (t < 128) atomicAdd(&g_r1[t], s[t]);
}

// ---------------- r_t = r1 @ D2 (128x256) ----------------
__global__ void rt_kernel(const float* __restrict__ D2) {
    __shared__ float red[256];
    int t = threadIdx.x;
    int lane = t & 31, ks = t >> 5;
    int c = blockIdx.x * 32 + lane;
    float s = 0.f;
    for (int k = ks * 16; k < ks * 16 + 16; k++) s = fmaf(g_r1[k], D2[(size_t)k * 256 + c], s);
    red[t] = s;
    __syncthreads();
    if (ks == 0) {
        float v = 0.f;
        for (int j = 0; j < 8; j++) v += red[j * 32 + lane];
        g_rt[c] = v;
    }
}

// ---------------- q_t = [inputs, r_t] @ CK ; s_t = inputs @ rec[:128] ----------------
__global__ void qs_kernel(const float* __restrict__ inp, const float* __restrict__ ck,
                          const float* __restrict__ rec) {
    __shared__ float red[256];
    int b = blockIdx.x;
    int t = threadIdx.x;
    int lane = t & 31, ks = t >> 5;
    if (b < 8) {
        int c = b * 32 + lane;
        float s = 0.f;
        for (int k = ks * 48; k < ks * 48 + 48; k++) {
            float v = (k < 128) ? inp[k] : g_rt[k - 128];
            s = fmaf(v, ck[(size_t)k * 256 + c], s);
        }
        red[t] = s;
        __syncthreads();
        if (ks == 0) {
            float v = 0.f;
            for (int j = 0; j < 8; j++) v += red[j * 32 + lane];
            g_qt[c] = v;
        }
    } else {
        int c = (b - 8) * 32 + lane;
        float s = 0.f;
        for (int k = ks * 16; k < ks * 16 + 16; k++)
            s = fmaf(inp[k], rec[(size_t)k * 256 + c], s);
        red[t] = s;
        __syncthreads();
        if (ks == 0) {
            float v = 0.f;
            for (int j = 0; j < 8; j++) v += red[j * 32 + lane];
            g_st[c] = v;
        }
    }
}

// ---------------- scores[p] = q_t . memory[p,:] ----------------
__global__ void scores_kernel(const float* __restrict__ mem) {
    __shared__ float sq[256];
    int t = threadIdx.x;
    sq[t] = g_qt[t];
    __syncthreads();
    int wq = t >> 5, lane = t & 31;
    int p = blockIdx.x * 8 + wq;
    const float4* mp = (const float4*)(mem + (size_t)p * 256);
    const float4* qp = (const float4*)sq;
    float s = 0.f;
#pragma unroll
    for (int k = 0; k < 2; k++) {
        float4 a = mp[lane * 2 + k];
        float4 q = qp[lane * 2 + k];
        s += a.x * q.x + a.y * q.y + a.z * q.z + a.w * q.w;
    }
    for (int off = 16; off; off >>= 1) s += __shfl_down_sync(0xffffffffu, s, off);
    if (lane == 0) g_scores[p] = s;
}

// ---------------- softmax over 4096 ----------------
__global__ void softmax_kernel() {
    __shared__ float red[256];
    int t = threadIdx.x;
    float m = -1e30f;
    for (int i = t; i < 4096; i += 256) m = fmaxf(m, g_scores[i]);
    red[t] = m;
    __syncthreads();
    for (int s = 128; s > 0; s >>= 1) {
        if (t < s) red[t] = fmaxf(red[t], red[t + s]);
        __syncthreads();
    }
    float mx = red[0];
    __syncthreads();
    float sum = 0.f;
    for (int i = t; i < 4096; i += 256) {
        float e = expf(g_scores[i] - mx);
        g_at[i] = e;
        sum += e;
    }
    red[t] = sum;
    __syncthreads();
    for (int s = 128; s > 0; s >>= 1) {
        if (t < s) red[t] += red[t + s];
        __syncthreads();
    }
    float inv = 1.f / red[0];
    for (int i = t; i < 4096; i += 256) g_at[i] *= inv;
}

// ---------------- c_t[c] = sum_p at[p]*memory[p][c] ----------------
__global__ void ct_kernel(const float* __restrict__ mem) {
    int t = threadIdx.x;
    int col4 = t & 63;
    int pr = t >> 6;  // 4 p-groups
    int p0 = blockIdx.x * 32;
    float4 acc = make_float4(0.f, 0.f, 0.f, 0.f);
    for (int i = 0; i < 8; i++) {
        int p = p0 + pr * 8 + i;
        float a = g_at[p];
        float4 m = ((const float4*)(mem + (size_t)p * 256))[col4];
        acc.x = fmaf(a, m.x, acc.x);
        acc.y = fmaf(a, m.y, acc.y);
        acc.z = fmaf(a, m.z, acc.z);
        acc.w = fmaf(a, m.w, acc.w);
    }
    __shared__ float4 sred[256];
    sred[t] = acc;
    __syncthreads();
    if (pr == 0) {
        float4 r = sred[col4];
        float4 a1 = sred[64 + col4], a2 = sred[128 + col4], a3 = sred[192 + col4];
        r.x += a1.x + a2.x + a3.x;
        r.y += a1.y + a2.y + a3.y;
        r.z += a1.z + a2.z + a3.z;
        r.w += a1.w + a2.w + a3.w;
        atomicAdd(&g_ct[col4 * 4 + 0], r.x);
        atomicAdd(&g_ct[col4 * 4 + 1], r.y);
        atomicAdd(&g_ct[col4 * 4 + 2], r.z);
        atomicAdd(&g_ct[col4 * 4 + 3], r.w);
    }
}

// ---------------- final: importances + mem_t update ----------------
__global__ void final_kernel(const float* __restrict__ mem, const float* __restrict__ rec,
                             const int* __restrict__ xp, const int* __restrict__ yp) {
    __shared__ float sdiff[256];
    __shared__ float red[256];
    int t = threadIdx.x;
    int pix = xp[0] * 64 + yp[0];
    float st = g_st[t];
    float m0 = mem[(size_t)pix * 256 + t];
    sdiff[t] = m0 - st;
    red[t] = st * g_rt[t];
    __syncthreads();
    for (int s = 128; s > 0; s >>= 1) {
        if (t < s) red[t] += red[t + s];
        __syncthreads();
    }
    float gi = red[0];
    __syncthreads();
    red[t] = st * g_ct[t];
    __syncthreads();
    for (int s = 128; s > 0; s >>= 1) {
        if (t < s) red[t] += red[t + s];
        __syncthreads();
    }
    float li = red[0];
    __syncthreads();
    float coef = li / (li + gi);
    int c = blockIdx.x * 32 + (t & 31);
    int ks = t >> 5;
    float d = 0.f;
    for (int k = ks * 32; k < ks * 32 + 32; k++)
        d = fmaf(sdiff[k], rec[(size_t)(128 + k) * 256 + c], d);
    red[t] = d;
    __syncthreads();
    if (ks == 0) {
        float v = 0.f;
        for (int j = 0; j < 8; j++) v += red[j * 32 + t];
        g_memt[c] = mem[(size_t)pix * 256 + c] + coef * v;
    }
}

// ---------------- write out: header + transposed new_mem ----------------
__global__ void writeout_kernel(const float* __restrict__ mem, float* __restrict__ out,
                                const int* __restrict__ xp, const int* __restrict__ yp) {
    __shared__ float tile[32][33];
    int pix0 = blockIdx.x * 32;
    int c0 = blockIdx.y * 32;
    int tx = threadIdx.x;  // 0..31
    int ty = threadIdx.y;  // 0..7
    int target = xp[0] * 64 + yp[0];
#pragma unroll
    for (int i = 0; i < 32; i += 8) {
        int p = pix0 + ty + i;
        tile[ty + i][tx] = mem[(size_t)p * 256 + c0 + tx];
    }
    __syncthreads();
#pragma unroll
    for (int i = 0; i < 32; i += 8) {
        int c = c0 + ty + i;
        int p = pix0 + tx;
        float v = tile[tx][ty + i];
        if (p == target) v = g_memt[c];
        out[512 + (size_t)c * 4096 + p] = v;
    }
    if (blockIdx.x == 0 && blockIdx.y == 0) {
        int t = ty * 32 + tx;
        out[t] = g_ct[t];
        out[256 + t] = g_rt[t];
    }
}

// ---------------- launch ----------------
extern "C" void kernel_launch(void* const* d_in, const int* in_sizes, int n_in,
                              void* d_out, int out_size) {
    const float* inp = (const float*)d_in[0];
    const float* mem = (const float*)d_in[1];
    const float* k1 = (const float*)d_in[2];
    const float* k2 = (const float*)d_in[3];
    const float* D1 = (const float*)d_in[4];
    const float* D2 = (const float*)d_in[5];
    const float* ck = (const float*)d_in[6];
    const float* rec = (const float*)d_in[7];
    const int* xp = (const int*)d_in[8];
    const int* yp = (const int*)d_in[9];
    float* out = (float*)d_out;

    zero_kernel<<<512, 256>>>();
    conv1_kernel<<<dim3(64, 8), 256>>>(mem, k1);
    conv2_kernel<<<dim3(62, 2), 256>>>(k2);
    pool_kernel<<<(FLATN + 255) / 256, 256>>>();
    dense1_kernel<<<296, 256>>>(D1);
    rt_kernel<<<8, 256>>>(D2);
    qs_kernel<<<16, 256>>>(inp, ck, rec);
    scores_kernel<<<512, 256>>>(mem);
    softmax_kernel<<<1, 256>>>();
    ct_kernel<<<128, 256>>>(mem);
    final_kernel<<<8, 256>>>(mem, rec, xp, yp);
    writeout_kernel<<<dim3(128, 8), dim3(32, 8)>>>(mem, out, xp, yp);
}

// round 2
// speedup vs baseline: 1.2706x; 1.2706x over previous
#include <cuda_runtime.h>
#include <math.h>

// inputs (metadata order):
// 0 inputs (1,128) f32        1 memory (4096,256) f32
// 2 conv_kernel1 (3,3,256,32) 3 conv_kernel2 (3,3,32,64)
// 4 conv_dense1 (238144,128)  5 conv_dense2 (128,256)
// 6 context_kernel (384,256)  7 recurr_kernel (384,256)
// 8 x (int)                   9 y (int)
// out: [c_t(256), r_t(256), new_mem(256*4096)] = 1049088 f32

#define FLATN 238144
typedef unsigned long long u64;

// ---------------- device scratch ----------------
__device__ float g_c1p[4][4096 * 32];  // conv1 partial sums per ci-chunk: [pixel*32+co]
__device__ float g_c2[64 * 62 * 62];   // [co2][i][j]
__device__ float g_r1[128];
__device__ float g_rt[256];
__device__ float g_qt[256];
__device__ float g_st[256];
__device__ float g_scores[4096];
__device__ float g_at[4096];
__device__ float g_ct[256];

// ---------------- f32x2 helpers ----------------
__device__ __forceinline__ u64 ffma2(u64 a, u64 b, u64 c) {
    u64 d;
    asm("fma.rn.f32x2 %0, %1, %2, %3;" : "=l"(d) : "l"(a), "l"(b), "l"(c));
    return d;
}
__device__ __forceinline__ u64 pack2(float x, float y) {
    u64 r;
    asm("mov.b64 %0, {%1,%2};" : "=l"(r) : "f"(x), "f"(y));
    return r;
}
__device__ __forceinline__ float2 unpack2(u64 v) {
    float2 r;
    asm("mov.b64 {%0,%1}, %2;" : "=f"(r.x), "=f"(r.y) : "l"(v));
    return r;
}

// ---------------- conv1: 3x3 SAME, 256->32, f32x2 over ci-pairs ----------------
// grid (64 rows, 4 ci-chunks of 64), block 256. lane = co, warp wq -> pixels w=wq*8..+7.
// smem input [r][wp][pair] (pair fastest: conflict-free STS, broadcast LDS).
__global__ void conv1_kernel(const float* __restrict__ mem, const float* __restrict__ k1) {
    __shared__ u64 s_in[3 * 68 * 8];
    __shared__ u64 s_wt[8 * 9 * 32];
    int h = blockIdx.x, chunk = blockIdx.y;
    int t = threadIdx.x, lane = t & 31, wq = t >> 5;
    if (h == 0 && chunk == 0) {   // zero small accumulators used by later kernels
        if (t < 128) g_r1[t] = 0.f;
        g_ct[t] = 0.f;
    }
    u64 acc[8];
#pragma unroll
    for (int p = 0; p < 8; p++) acc[p] = 0ull;

    for (int sub = 0; sub < 4; sub++) {
        int ci0 = chunk * 64 + sub * 16;
        // weights: pack (ci, ci+1) per co
        for (int i = t; i < 8 * 9 * 32; i += 256) {
            int co = i & 31;
            int kk = (i >> 5) % 9;
            int pr = i / 288;
            int ci = ci0 + 2 * pr;
            s_wt[i] = pack2(k1[((size_t)kk * 256 + ci) * 32 + co],
                            k1[((size_t)kk * 256 + ci + 1) * 32 + co]);
        }
        // inputs: contiguous ci-pair loads straight from gmem
        for (int i = t; i < 8 * 3 * 66; i += 256) {
            int pr = i & 7;
            int rest = i >> 3;
            int wp = rest % 66;
            int r = rest / 66;
            int hh = h + r - 1, ww = wp - 1;
            u64 v = 0ull;
            if (hh >= 0 && hh < 64 && ww >= 0 && ww < 64)
                v = *(const u64*)&mem[((size_t)hh * 64 + ww) * 256 + ci0 + 2 * pr];
            s_in[(r * 68 + wp) * 8 + pr] = v;
        }
        __syncthreads();
#pragma unroll 1
        for (int pr = 0; pr < 8; pr++) {
            u64 w[9];
#pragma unroll
            for (int kk = 0; kk < 9; kk++) w[kk] = s_wt[pr * 288 + kk * 32 + lane];
#pragma unroll
            for (int r = 0; r < 3; r++) {
                u64 inv[10];
#pragma unroll
                for (int j = 0; j < 10; j++) inv[j] = s_in[(r * 68 + wq * 8 + j) * 8 + pr];
#pragma unroll
                for (int kw = 0; kw < 3; kw++) {
                    u64 wv = w[r * 3 + kw];
#pragma unroll
                    for (int p = 0; p < 8; p++) acc[p] = ffma2(inv[p + kw], wv, acc[p]);
                }
            }
        }
        __syncthreads();
    }
#pragma unroll
    for (int p = 0; p < 8; p++) {
        float2 a = unpack2(acc[p]);
        g_c1p[chunk][((size_t)h * 64 + wq * 8 + p) * 32 + lane] = a.x + a.y;
    }
}

// ---------------- conv2: 3x3 VALID, 32->64, f32x2, sums 4 conv1 partials ----------------
// grid (62 rows, 2 co-halves), block 256.
__global__ void conv2_kernel(const float* __restrict__ k2) {
    __shared__ u64 s_in[3 * 68 * 8];
    __shared__ u64 s_wt[8 * 9 * 32];
    int i0 = blockIdx.x, half = blockIdx.y;
    int t = threadIdx.x, lane = t & 31, wq = t >> 5;
    u64 acc[8];
#pragma unroll
    for (int p = 0; p < 8; p++) acc[p] = 0ull;

    for (int sub = 0; sub < 2; sub++) {
        int ci0 = sub * 16;
        for (int i = t; i < 8 * 9 * 32; i += 256) {
            int co = i & 31;
            int kk = (i >> 5) % 9;
            int pr = i / 288;
            int ci = ci0 + 2 * pr;
            s_wt[i] = pack2(k2[((size_t)kk * 32 + ci) * 64 + half * 32 + co],
                            k2[((size_t)kk * 32 + ci + 1) * 64 + half * 32 + co]);
        }
        for (int i = t; i < 8 * 3 * 66; i += 256) {
            int pr = i & 7;
            int rest = i >> 3;
            int wp = rest % 66;
            int r = rest / 66;
            u64 v = 0ull;
            if (wp < 64) {
                size_t pix = (size_t)(i0 + r) * 64 + wp;
                float2 a0 = *(const float2*)&g_c1p[0][pix * 32 + ci0 + 2 * pr];
                float2 a1 = *(const float2*)&g_c1p[1][pix * 32 + ci0 + 2 * pr];
                float2 a2 = *(const float2*)&g_c1p[2][pix * 32 + ci0 + 2 * pr];
                float2 a3 = *(const float2*)&g_c1p[3][pix * 32 + ci0 + 2 * pr];
                v = pack2(a0.x + a1.x + a2.x + a3.x, a0.y + a1.y + a2.y + a3.y);
            }
            s_in[(r * 68 + wp) * 8 + pr] = v;
        }
        __syncthreads();
#pragma unroll 1
        for (int pr = 0; pr < 8; pr++) {
            u64 w[9];
#pragma unroll
            for (int kk = 0; kk < 9; kk++) w[kk] = s_wt[pr * 288 + kk * 32 + lane];
#pragma unroll
            for (int r = 0; r < 3; r++) {
                u64 inv[10];
#pragma unroll
                for (int j = 0; j < 10; j++) inv[j] = s_in[(r * 68 + wq * 8 + j) * 8 + pr];
#pragma unroll
                for (int kw = 0; kw < 3; kw++) {
                    u64 wv = w[r * 3 + kw];
#pragma unroll
                    for (int p = 0; p < 8; p++) acc[p] = ffma2(inv[p + kw], wv, acc[p]);
                }
            }
        }
        __syncthreads();
    }
    int co2 = half * 32 + lane;
#pragma unroll
    for (int p = 0; p < 8; p++) {
        int j = wq * 8 + p;
        float2 a = unpack2(acc[p]);
        if (j < 62) g_c2[(size_t)co2 * 3844 + i0 * 62 + j] = a.x + a.y;
    }
}

// ---------------- dense1: r1[128] = (pool of c2) @ D1 (122 MB stream) ----------------
#define D1GRID 592
__global__ void dense1_kernel(const float* __restrict__ D1) {
    int t = threadIdx.x;
    int wq = t >> 5, lane = t & 31;
    float4 acc = make_float4(0.f, 0.f, 0.f, 0.f);
    const float4* D4 = (const float4*)D1;
    for (int row = blockIdx.x * 8 + wq; row < FLATN; row += D1GRID * 8) {
        int c = row / 3721;
        int rem = row - c * 3721;
        int ph = rem / 61;
        int pw = rem - ph * 61;
        const float* b = &g_c2[(size_t)c * 3844 + ph * 62 + pw];
        float v = 0.25f * (b[0] + b[1] + b[62] + b[63]);
        float4 d = __ldcs(D4 + (size_t)row * 32 + lane);
        acc.x = fmaf(v, d.x, acc.x);
        acc.y = fmaf(v, d.y, acc.y);
        acc.z = fmaf(v, d.z, acc.z);
        acc.w = fmaf(v, d.w, acc.w);
    }
    __shared__ float s[128];
    if (t < 128) s[t] = 0.f;
    __syncthreads();
    atomicAdd(&s[lane * 4 + 0], acc.x);
    atomicAdd(&s[lane * 4 + 1], acc.y);
    atomicAdd(&s[lane * 4 + 2], acc.z);
    atomicAdd(&s[lane * 4 + 3], acc.w);
    __syncthreads();
    if (t < 128) atomicAdd(&g_r1[t], s[t]);
}

// ---------------- r_t = r1 @ D2 (128x256) ----------------
__global__ void rt_kernel(const float* __restrict__ D2) {
    __shared__ float red[256];
    int t = threadIdx.x;
    int lane = t & 31, ks = t >> 5;
    int c = blockIdx.x * 32 + lane;
    float s = 0.f;
    for (int k = ks * 16; k < ks * 16 + 16; k++) s = fmaf(g_r1[k], D2[(size_t)k * 256 + c], s);
    red[t] = s;
    __syncthreads();
    if (ks == 0) {
        float v = 0.f;
        for (int j = 0; j < 8; j++) v += red[j * 32 + lane];
        g_rt[c] = v;
    }
}

// ---------------- q_t = [inputs, r_t] @ CK ; s_t = inputs @ rec[:128] ----------------
__global__ void qs_kernel(const float* __restrict__ inp, const float* __restrict__ ck,
                          const float* __restrict__ rec) {
    __shared__ float red[256];
    int b = blockIdx.x;
    int t = threadIdx.x;
    int lane = t & 31, ks = t >> 5;
    if (b < 8) {
        int c = b * 32 + lane;
        float s = 0.f;
        for (int k = ks * 48; k < ks * 48 + 48; k++) {
            float v = (k < 128) ? inp[k] : g_rt[k - 128];
            s = fmaf(v, ck[(size_t)k * 256 + c], s);
        }
        red[t] = s;
        __syncthreads();
        if (ks == 0) {
            float v = 0.f;
            for (int j = 0; j < 8; j++) v += red[j * 32 + lane];
            g_qt[c] = v;
        }
    } else {
        int c = (b - 8) * 32 + lane;
        float s = 0.f;
        for (int k = ks * 16; k < ks * 16 + 16; k++)
            s = fmaf(inp[k], rec[(size_t)k * 256 + c], s);
        red[t] = s;
        __syncthreads();
        if (ks == 0) {
            float v = 0.f;
            for (int j = 0; j < 8; j++) v += red[j * 32 + lane];
            g_st[c] = v;
        }
    }
}

// ---------------- scores[p] = q_t . memory[p,:] ----------------
__global__ void scores_kernel(const float* __restrict__ mem) {
    __shared__ float sq[256];
    int t = threadIdx.x;
    sq[t] = g_qt[t];
    __syncthreads();
    int wq = t >> 5, lane = t & 31;
    int p = blockIdx.x * 8 + wq;
    const float4* mp = (const float4*)(mem + (size_t)p * 256);
    const float4* qp = (const float4*)sq;
    float s = 0.f;
#pragma unroll
    for (int k = 0; k < 2; k++) {
        float4 a = mp[lane * 2 + k];
        float4 q = qp[lane * 2 + k];
        s += a.x * q.x + a.y * q.y + a.z * q.z + a.w * q.w;
    }
    for (int off = 16; off; off >>= 1) s += __shfl_down_sync(0xffffffffu, s, off);
    if (lane == 0) g_scores[p] = s;
}

// ---------------- softmax over 4096 ----------------
__global__ void softmax_kernel() {
    __shared__ float red[256];
    int t = threadIdx.x;
    float m = -1e30f;
    for (int i = t; i < 4096; i += 256) m = fmaxf(m, g_scores[i]);
    red[t] = m;
    __syncthreads();
    for (int s = 128; s > 0; s >>= 1) {
        if (t < s) red[t] = fmaxf(red[t], red[t + s]);
        __syncthreads();
    }
    float mx = red[0];
    __syncthreads();
    float sum = 0.f;
    for (int i = t; i < 4096; i += 256) {
        float e = expf(g_scores[i] - mx);
        g_at[i] = e;
        sum += e;
    }
    red[t] = sum;
    __syncthreads();
    for (int s = 128; s > 0; s >>= 1) {
        if (t < s) red[t] += red[t + s];
        __syncthreads();
    }
    float inv = 1.f / red[0];
    for (int i = t; i < 4096; i += 256) g_at[i] *= inv;
}

// ---------------- c_t[c] = sum_p at[p]*memory[p][c] ----------------
__global__ void ct_kernel(const float* __restrict__ mem) {
    int t = threadIdx.x;
    int col4 = t & 63;
    int pr = t >> 6;
    int p0 = blockIdx.x * 32;
    float4 acc = make_float4(0.f, 0.f, 0.f, 0.f);
    for (int i = 0; i < 8; i++) {
        int p = p0 + pr * 8 + i;
        float a = g_at[p];
        float4 m = ((const float4*)(mem + (size_t)p * 256))[col4];
        acc.x = fmaf(a, m.x, acc.x);
        acc.y = fmaf(a, m.y, acc.y);
        acc.z = fmaf(a, m.z, acc.z);
        acc.w = fmaf(a, m.w, acc.w);
    }
    __shared__ float4 sred[256];
    sred[t] = acc;
    __syncthreads();
    if (pr == 0) {
        float4 r = sred[col4];
        float4 a1 = sred[64 + col4], a2 = sred[128 + col4], a3 = sred[192 + col4];
        r.x += a1.x + a2.x + a3.x;
        r.y += a1.y + a2.y + a3.y;
        r.z += a1.z + a2.z + a3.z;
        r.w += a1.w + a2.w + a3.w;
        atomicAdd(&g_ct[col4 * 4 + 0], r.x);
        atomicAdd(&g_ct[col4 * 4 + 1], r.y);
        atomicAdd(&g_ct[col4 * 4 + 2], r.z);
        atomicAdd(&g_ct[col4 * 4 + 3], r.w);
    }
}

// ---------------- write out: header + transposed new_mem + fused final update ----------------
__global__ void writeout_kernel(const float* __restrict__ mem, const float* __restrict__ rec,
                                float* __restrict__ out,
                                const int* __restrict__ xp, const int* __restrict__ yp) {
    __shared__ float tile[32][33];
    __shared__ float s_memt[32];
    __shared__ float red[256];
    __shared__ float sdiff[256];
    int pix0 = blockIdx.x * 32;
    int c0 = blockIdx.y * 32;
    int tx = threadIdx.x;  // 0..31
    int ty = threadIdx.y;  // 0..7
    int t = ty * 32 + tx;
    int target = xp[0] * 64 + yp[0];

    if ((target >> 5) == (int)blockIdx.x) {
        // this block owns the target pixel: compute mem_t for our 32 channels
        float st = g_st[t];
        sdiff[t] = mem[(size_t)target * 256 + t] - st;
        red[t] = st * g_rt[t];
        __syncthreads();
        for (int s = 128; s > 0; s >>= 1) {
            if (t < s) red[t] += red[t + s];
            __syncthreads();
        }
        float gi = red[0];
        __syncthreads();
        red[t] = st * g_ct[t];
        __syncthreads();
        for (int s = 128; s > 0; s >>= 1) {
            if (t < s) red[t] += red[t + s];
            __syncthreads();
        }
        float li = red[0];
        __syncthreads();
        float coef = li / (li + gi);
        int cl = t & 31, ks = t >> 5;
        float d = 0.f;
        for (int k = ks * 32; k < ks * 32 + 32; k++)
            d = fmaf(sdiff[k], rec[(size_t)(128 + k) * 256 + c0 + cl], d);
        red[t] = d;
        __syncthreads();
        if (t < 32) {
            float v = 0.f;
            for (int j = 0; j < 8; j++) v += red[j * 32 + t];
            s_memt[t] = mem[(size_t)target * 256 + c0 + t] + coef * v;
        }
        __syncthreads();
    }

#pragma unroll
    for (int i = 0; i < 32; i += 8) {
        int p = pix0 + ty + i;
        tile[ty + i][tx] = mem[(size_t)p * 256 + c0 + tx];
    }
    __syncthreads();
#pragma unroll
    for (int i = 0; i < 32; i += 8) {
        int c = c0 + ty + i;
        int p = pix0 + tx;
        float v = tile[tx][ty + i];
        if (p == target) v = s_memt[ty + i];
        out[512 + (size_t)c * 4096 + p] = v;
    }
    if (blockIdx.x == 0 && blockIdx.y == 0) {
        out[t] = g_ct[t];
        out[256 + t] = g_rt[t];
    }
}

// ---------------- launch ----------------
extern "C" void kernel_launch(void* const* d_in, const int* in_sizes, int n_in,
                              void* d_out, int out_size) {
    const float* inp = (const float*)d_in[0];
    const float* mem = (const float*)d_in[1];
    const float* k1 = (const float*)d_in[2];
    const float* k2 = (const float*)d_in[3];
    const float* D1 = (const float*)d_in[4];
    const float* D2 = (const float*)d_in[5];
    const float* ck = (const float*)d_in[6];
    const float* rec = (const float*)d_in[7];
    const int* xp = (const int*)d_in[8];
    const int* yp = (const int*)d_in[9];
    float* out = (float*)d_out;

    conv1_kernel<<<dim3(64, 4), 256>>>(mem, k1);
    conv2_kernel<<<dim3(62, 2), 256>>>(k2);
    dense1_kernel<<<D1GRID, 256>>>(D1);
    rt_kernel<<<8, 256>>>(D2);
    qs_kernel<<<16, 256>>>(inp, ck, rec);
    scores_kernel<<<512, 256>>>(mem);
    softmax_kernel<<<1, 256>>>();
    ct_kernel<<<128, 256>>>(mem);
    writeout_kernel<<<dim3(128, 8), dim3(32, 8)>>>(mem, rec, out, xp, yp);
}